// round 14
// baseline (speedup 1.0000x reference)
#include <cuda_runtime.h>
#include <cstdint>

#define SGX 32
#define SGY 24
#define SGT 5
#define NBINS (2 * SGT * SGY * SGX)   // 7680

#define GRID    296
#define NPROD   148
#define THREADS 1024
#define SEGW    8192                  // words per segment (2 events/word)

#define N_MAX     16777216
#define TQ_MAXI   2097151u
#define TQ_SCALE  (2097151.0f / 50.0f)   // t in [0,50] -> [0, 2^21-1]
#define C_FIXED   (5.0f / 2097152.0f)    // exact 5*2^-21
#define GUARD_U   1280u                  // guard band in u = 5*tq space
#define CHECK_DEV 1000ll                 // |5*bk - k*2^21| <= this (< GUARD_U)
#define SENT      0xFFFFu
#define BUF_CAP   (1u << 20)             // sentinel index buffer (exp ~20k)

__device__ uint32_t     g_code[N_MAX / 2 + 8];   // 32 MB u16-code pairs
__device__ unsigned int g_sbuf[BUF_CAP];         // sentinel EVENT indices
__device__ unsigned int g_counts[NBINS];         // fast-path histogram
__device__ unsigned int g_counts2[NBINS];        // slow-path histogram
__device__ unsigned int g_bqmin[NPROD];
__device__ unsigned int g_bqmax[NPROD];
__device__ unsigned int g_prog[NPROD];           // per-producer segment doorbell
__device__ unsigned int g_sbufcnt, g_arrive, g_exit;

// u16 speculative bin code (SENT if near fixed threshold k*2^21/5) + quantized t
__device__ __forceinline__ unsigned int decode_code(float4 e, unsigned int& tq) {
    int xv = min(max((int)(e.x * 0.05f), 0), SGX - 1);
    int yv = min(max((int)(e.y * 0.05f), 0), SGY - 1);
    float tf = fmaxf(fmaf(e.z, TQ_SCALE, 0.5f), 0.0f);
    tq = min((unsigned int)tf, TQ_MAXI);
    unsigned int p = (e.w > 0.0f) ? 0u : 1u;
    unsigned int sp = p * 3840u + (unsigned int)yv * 32u + (unsigned int)xv;
    unsigned int u = tq * 5u;
    bool bdry = ((u + GUARD_U) & 0x1FFFFFu) < 2u * GUARD_U;
    int tv = (int)((float)tq * C_FIXED);            // exact floor(5*tq/2^21)
    return bdry ? SENT : ((unsigned int)tv * 768u + sp);
}

__device__ __forceinline__ int bin_exact(float4 e, unsigned int b1, unsigned int b2,
                                         unsigned int b3, unsigned int b4) {
    int xv = min(max((int)(e.x * 0.05f), 0), SGX - 1);
    int yv = min(max((int)(e.y * 0.05f), 0), SGY - 1);
    float tf = fmaxf(fmaf(e.z, TQ_SCALE, 0.5f), 0.0f);
    unsigned int tq = min((unsigned int)tf, TQ_MAXI);
    unsigned int p = (e.w > 0.0f) ? 0u : 1u;
    int tv = (int)(tq >= b1) + (int)(tq >= b2) + (int)(tq >= b3) + (int)(tq >= b4);
    return tv * 768 + (int)(p * 3840u) + yv * SGX + xv;
}

__device__ __forceinline__ void sent_append(int idx, int n) {
    if (idx < n) {
        unsigned int slot = atomicAdd(&g_sbufcnt, 1u);
        if (slot < BUF_CAP) g_sbuf[slot] = (unsigned int)idx;
    }
}

__global__ __launch_bounds__(THREADS, 2)
void voxel_kernel(const float4* __restrict__ ev, int n, int W, int nseg,
                  float* __restrict__ out, float inv_s) {
    __shared__ unsigned int sh[NBINS];
    __shared__ unsigned int smin[32], smax[32];
    __shared__ unsigned int s_b1, s_b2, s_b3, s_b4, s_cnt;
    __shared__ int s_fast;
    __shared__ bool s_last;

    const int tid = threadIdx.x;
    const int nwords = (n + 1) >> 1;
    const bool prod = (blockIdx.x < NPROD);

    if (prod) {
        // ===================== PRODUCER =====================
        const int b = blockIdx.x;
        const int wbeg = b * W;
        const int wend = min(nwords, wbeg + W);
        unsigned int tqmin = 0xFFFFFFFFu, tqmax = 0u;

        for (int s = 0; s < nseg; s++) {
            int base = wbeg + s * SEGW;
            int cnt = min(SEGW, wend - base);
            if (cnt > 0) {
                if (cnt == SEGW && 2 * (base + SEGW) <= n) {
                    #pragma unroll 2
                    for (int k = 0; k < 8; k++) {
                        int w = base + tid + (k << 10);
                        float4 ea = __ldcs(ev + 2 * w);
                        float4 eb = __ldcs(ev + 2 * w + 1);
                        unsigned int ta, tb;
                        unsigned int c = decode_code(ea, ta) | (decode_code(eb, tb) << 16);
                        g_code[w] = c;
                        tqmin = min(tqmin, min(ta, tb));
                        tqmax = max(tqmax, max(ta, tb));
                    }
                } else {
                    #pragma unroll 1
                    for (int w = base + tid; w < base + cnt; w += THREADS) {
                        int i0 = 2 * w;
                        float4 ea = __ldcs(ev + i0);
                        unsigned int ta;
                        unsigned int c = decode_code(ea, ta);
                        tqmin = min(tqmin, ta); tqmax = max(tqmax, ta);
                        unsigned int chi = SENT;   // pad: consumer bounds-checks
                        if (i0 + 1 < n) {
                            float4 eb = __ldcs(ev + i0 + 1);
                            unsigned int tb;
                            chi = decode_code(eb, tb);
                            tqmin = min(tqmin, tb); tqmax = max(tqmax, tb);
                        }
                        g_code[w] = c | (chi << 16);
                    }
                }
            }
            __threadfence();                 // publish this segment's codes
            __syncthreads();
            if (tid == 0) *(volatile unsigned int*)&g_prog[b] = (unsigned int)(s + 1);
        }

        // qmin/qmax partials
        #pragma unroll
        for (int o = 16; o > 0; o >>= 1) {
            tqmin = min(tqmin, __shfl_xor_sync(0xFFFFFFFFu, tqmin, o));
            tqmax = max(tqmax, __shfl_xor_sync(0xFFFFFFFFu, tqmax, o));
        }
        int wid = tid >> 5, lid = tid & 31;
        if (lid == 0) { smin[wid] = tqmin; smax[wid] = tqmax; }
        __syncthreads();
        if (tid == 0) {
            unsigned int m0 = smin[0], m1 = smax[0];
            for (int w = 1; w < (THREADS >> 5); w++) { m0 = min(m0, smin[w]); m1 = max(m1, smax[w]); }
            g_bqmin[b] = m0;
            g_bqmax[b] = m1;
        }
    } else {
        // ===================== CONSUMER =====================
        const int b = blockIdx.x - NPROD;    // paired producer
        const int wbeg = b * W;
        const int wend = min(nwords, wbeg + W);
        for (int i = tid; i < NBINS; i += THREADS) sh[i] = 0u;
        __syncthreads();

        for (int s = 0; s < nseg; s++) {
            int base = wbeg + s * SEGW;
            int cnt = min(SEGW, wend - base);
            if (cnt <= 0) break;
            if (tid == 0) {
                volatile unsigned int* vp = &g_prog[b];
                while (*vp <= (unsigned int)s) __nanosleep(128);
                __threadfence();             // acquire
            }
            __syncthreads();

            if (cnt == SEGW && 2 * (base + SEGW) <= n) {
                const uint4* p4 = reinterpret_cast<const uint4*>(g_code + base);
                #pragma unroll
                for (int h = 0; h < 2; h++) {
                    int qi = tid + (h << 10);
                    uint4 a = __ldcg(p4 + qi);
                    int wb = base + 4 * qi;
                    #pragma unroll
                    for (int j = 0; j < 4; j++) {
                        unsigned int x = (&a.x)[j];
                        unsigned int v0 = x & 0xFFFFu, v1 = x >> 16;
                        if (v0 != SENT) atomicAdd(&sh[v0], 1u); else sent_append(2 * (wb + j), n);
                        if (v1 != SENT) atomicAdd(&sh[v1], 1u); else sent_append(2 * (wb + j) + 1, n);
                    }
                }
            } else {
                #pragma unroll 1
                for (int w = base + tid; w < base + cnt; w += THREADS) {
                    unsigned int x = __ldcg(g_code + w);
                    unsigned int v0 = x & 0xFFFFu, v1 = x >> 16;
                    if (v0 != SENT) atomicAdd(&sh[v0], 1u); else sent_append(2 * w, n);
                    if (v1 != SENT) atomicAdd(&sh[v1], 1u); else sent_append(2 * w + 1, n);
                }
            }
        }
        __syncthreads();
        for (int i = tid; i < NBINS; i += THREADS) {
            unsigned int v = sh[i];
            if (v) atomicAdd(&g_counts[i], v);
        }
    }

    // ===================== grid barrier (all 296 resident) =====================
    __threadfence();
    __syncthreads();
    if (tid == 0) {
        atomicAdd(&g_arrive, 1u);
        volatile unsigned int* va = &g_arrive;
        while (*va < (unsigned int)GRID) __nanosleep(64);
        __threadfence();
    }
    __syncthreads();

    // exact thresholds + fast/slow decision
    if (tid == 0) {
        unsigned int m0 = 0xFFFFFFFFu, m1 = 0u;
        for (int k = 0; k < NPROD; k++) {
            m0 = min(m0, g_bqmin[k]);
            m1 = max(m1, g_bqmax[k]);
        }
        int fast = 1;
        unsigned int bb[5];
        if (m1 > m0) {
            unsigned long long range = (unsigned long long)(m1 - m0);
            for (unsigned long long k = 1; k <= 4; k++) {
                unsigned long long bk = (unsigned long long)m0 + (k * range + 4ull) / 5ull;
                long long dev = (long long)(5ull * bk) - (long long)(k << 21);
                if (dev < -CHECK_DEV || dev > CHECK_DEV) fast = 0;
                bb[k] = (unsigned int)bk;
            }
        } else {
            bb[1] = 419431u; bb[2] = 838861u; bb[3] = 1258291u; bb[4] = 1677721u;
        }
        unsigned int bc = *(volatile unsigned int*)&g_sbufcnt;
        if (bc > BUF_CAP) fast = 0;
        s_b1 = bb[1]; s_b2 = bb[2]; s_b3 = bb[3]; s_b4 = bb[4];
        s_cnt = min(bc, BUF_CAP);
        s_fast = fast;
    }
    __syncthreads();
    unsigned int b1 = s_b1, b2 = s_b2, b3 = s_b3, b4 = s_b4;
    int gstride = GRID * THREADS;
    int gbase = blockIdx.x * THREADS + tid;

    if (s_fast) {
        // fixup: sentinel events, exact thresholds, direct global adds
        int cnt = (int)s_cnt;
        for (int j = gbase; j < cnt; j += gstride) {
            unsigned int idx = g_sbuf[j];
            float4 e = __ldcs(ev + idx);
            atomicAdd(&g_counts[bin_exact(e, b1, b2, b3, b4)], 1u);
        }
    } else {
        // slow path: exact re-histogram of all events
        for (int i = tid; i < NBINS; i += THREADS) sh[i] = 0u;
        __syncthreads();
        for (int i = gbase; i < n; i += gstride) {
            atomicAdd(&sh[bin_exact(__ldcs(ev + i), b1, b2, b3, b4)], 1u);
        }
        __syncthreads();
        for (int i = tid; i < NBINS; i += THREADS) {
            unsigned int v = sh[i];
            if (v) atomicAdd(&g_counts2[i], v);
        }
    }

    // ===================== finalize + full state reset =====================
    __threadfence();
    __syncthreads();
    if (tid == 0) {
        unsigned int t = atomicAdd(&g_exit, 1u);
        s_last = (t == (unsigned int)GRID - 1u);
    }
    __syncthreads();
    if (s_last) {
        __threadfence();
        int fast = s_fast;
        for (int i = tid; i < NBINS; i += THREADS) {
            unsigned int c = fast ? g_counts[i] : g_counts2[i];
            out[i] = (float)c * inv_s;
            g_counts[i]  = 0u;
            g_counts2[i] = 0u;
        }
        for (int k = tid; k < NPROD; k += THREADS) g_prog[k] = 0u;
        if (tid == 0) {
            g_sbufcnt = 0u;
            g_arrive  = 0u;
            g_exit    = 0u;
            __threadfence();
        }
    }
}

extern "C" void kernel_launch(void* const* d_in, const int* in_sizes, int n_in,
                              void* d_out, int out_size) {
    const float4* ev = (const float4*)d_in[0];
    int n = in_sizes[0] / 4;              // events: (N, 4) f32, N = 2^24
    float* out = (float*)d_out;

    int nwords = (n + 1) / 2;
    int wper = (nwords + NPROD - 1) / NPROD;
    int W = ((wper + SEGW - 1) / SEGW) * SEGW;   // multiple of SEGW
    int nseg = W / SEGW;
    float inv_s = (n > 0) ? (1.0f / (float)n) : 1.0f;

    voxel_kernel<<<GRID, THREADS>>>(ev, n, W, nseg, out, inv_s);
}

// round 15
// speedup vs baseline: 1.1464x; 1.1464x over previous
#include <cuda_runtime.h>
#include <cstdint>

#define SGX 32
#define SGY 24
#define SGT 5
#define NBINS (2 * SGT * SGY * SGX)   // 7680

#define BLOCKS   296
#define THREADS1 512                  // pass1: occ 2, 64-reg budget for 8 float4 in flight
#define THREADS2 1024                 // pass2: full occupancy

#define N_MAX    16777216
#define TQ_MAXI   2097151u
#define TQ_SCALE  (2097151.0f / 50.0f)   // t in [0,50] -> [0, 2^21-1]
#define C_FIXED   (5.0f / 2097152.0f)    // exact 5*2^-21; tq*C_FIXED exact in f32
#define GUARD_U   1280u                  // guard band in u = 5*tq space
#define CHECK_DEV 1000ll                 // |5*bk - k*2^21| <= this  (< GUARD_U)
#define SENT      0xFFFFu

__device__ __align__(16) uint32_t g_code[N_MAX / 2 + 8];  // 32 MB u16-code pairs
__device__ unsigned int g_counts[NBINS];        // fast-path histogram
__device__ unsigned int g_counts2[NBINS];       // slow-path histogram
__device__ unsigned int g_bqmin[BLOCKS];
__device__ unsigned int g_bqmax[BLOCKS];
__device__ unsigned int g_done;

// u16 speculative bin code (SENT if within guard band of fixed threshold
// k*2^21/5), plus quantized t
__device__ __forceinline__ unsigned int decode_code(float4 e, unsigned int& tq) {
    int xv = min(max((int)(e.x * 0.05f), 0), SGX - 1);
    int yv = min(max((int)(e.y * 0.05f), 0), SGY - 1);
    float tf = fmaxf(fmaf(e.z, TQ_SCALE, 0.5f), 0.0f);
    tq = min((unsigned int)tf, TQ_MAXI);
    unsigned int p = (e.w > 0.0f) ? 0u : 1u;
    unsigned int sp = p * 3840u + (unsigned int)yv * 32u + (unsigned int)xv;
    unsigned int u = tq * 5u;
    bool bdry = ((u + GUARD_U) & 0x1FFFFFu) < 2u * GUARD_U;
    int tv = (int)((float)tq * C_FIXED);            // exact floor(5*tq/2^21)
    return bdry ? SENT : ((unsigned int)tv * 768u + sp);
}

// exact-threshold bin from a raw event (sentinel fixup + slow path)
__device__ __forceinline__ int bin_exact(float4 e, unsigned int b1, unsigned int b2,
                                         unsigned int b3, unsigned int b4) {
    int xv = min(max((int)(e.x * 0.05f), 0), SGX - 1);
    int yv = min(max((int)(e.y * 0.05f), 0), SGY - 1);
    float tf = fmaxf(fmaf(e.z, TQ_SCALE, 0.5f), 0.0f);
    unsigned int tq = min((unsigned int)tf, TQ_MAXI);
    unsigned int p = (e.w > 0.0f) ? 0u : 1u;
    int tv = (int)(tq >= b1) + (int)(tq >= b2) + (int)(tq >= b3) + (int)(tq >= b4);
    return tv * 768 + (int)(p * 3840u) + yv * SGX + xv;
}

// ---------------------------------------------------------------------------
// Pass 1: stream events (evict-first), emit u16 codes as STG.64 quads,
// per-block qmin/qmax partials; zero accumulators + done flag.
// One quad = 4 consecutive events = 2 code words = one uint2 store.
// ---------------------------------------------------------------------------
__global__ __launch_bounds__(THREADS1, 2)
void pass1_kernel(const float4* __restrict__ ev, int n) {
    int gtid = blockIdx.x * blockDim.x + threadIdx.x;
    int stride = gridDim.x * blockDim.x;
    for (int b = gtid; b < NBINS; b += stride) { g_counts[b] = 0u; g_counts2[b] = 0u; }
    if (gtid == 0) g_done = 0u;

    unsigned int tqmin = 0xFFFFFFFFu;
    unsigned int tqmax = 0u;
    int nq = n >> 2;                       // full quads
    uint2* code2 = reinterpret_cast<uint2*>(g_code);
    int q = gtid;

    for (; q + stride < nq; q += 2 * stride) {
        int qa = q, qb = q + stride;
        float4 a0 = __ldcs(ev + 4 * qa);     float4 a1 = __ldcs(ev + 4 * qa + 1);
        float4 a2 = __ldcs(ev + 4 * qa + 2); float4 a3 = __ldcs(ev + 4 * qa + 3);
        float4 b0 = __ldcs(ev + 4 * qb);     float4 b1 = __ldcs(ev + 4 * qb + 1);
        float4 b2 = __ldcs(ev + 4 * qb + 2); float4 b3 = __ldcs(ev + 4 * qb + 3);
        unsigned int t0, t1, t2, t3, t4, t5, t6, t7;
        unsigned int ca0 = decode_code(a0, t0), ca1 = decode_code(a1, t1);
        unsigned int ca2 = decode_code(a2, t2), ca3 = decode_code(a3, t3);
        unsigned int cb0 = decode_code(b0, t4), cb1 = decode_code(b1, t5);
        unsigned int cb2 = decode_code(b2, t6), cb3 = decode_code(b3, t7);
        code2[qa] = make_uint2(ca0 | (ca1 << 16), ca2 | (ca3 << 16));
        code2[qb] = make_uint2(cb0 | (cb1 << 16), cb2 | (cb3 << 16));
        tqmin = min(tqmin, min(min(t0, t1), min(t2, t3)));
        tqmin = min(tqmin, min(min(t4, t5), min(t6, t7)));
        tqmax = max(tqmax, max(max(t0, t1), max(t2, t3)));
        tqmax = max(tqmax, max(max(t4, t5), max(t6, t7)));
    }
    #pragma unroll 1
    for (; q < nq; q += stride) {
        float4 a0 = __ldcs(ev + 4 * q);     float4 a1 = __ldcs(ev + 4 * q + 1);
        float4 a2 = __ldcs(ev + 4 * q + 2); float4 a3 = __ldcs(ev + 4 * q + 3);
        unsigned int t0, t1, t2, t3;
        unsigned int c0 = decode_code(a0, t0), c1 = decode_code(a1, t1);
        unsigned int c2 = decode_code(a2, t2), c3 = decode_code(a3, t3);
        code2[q] = make_uint2(c0 | (c1 << 16), c2 | (c3 << 16));
        tqmin = min(tqmin, min(min(t0, t1), min(t2, t3)));
        tqmax = max(tqmax, max(max(t0, t1), max(t2, t3)));
    }
    // tail events [4*nq, n): exclusive word range, single thread, u16 stores
    if (gtid == 0) {
        for (int i = nq << 2; i < n; i++) {
            float4 e = __ldcs(ev + i);
            unsigned int t;
            reinterpret_cast<unsigned short*>(g_code)[i] =
                (unsigned short)decode_code(e, t);
            tqmin = min(tqmin, t);
            tqmax = max(tqmax, t);
        }
    }

    // block minmax reduce -> per-block partials
    #pragma unroll
    for (int o = 16; o > 0; o >>= 1) {
        tqmin = min(tqmin, __shfl_xor_sync(0xFFFFFFFFu, tqmin, o));
        tqmax = max(tqmax, __shfl_xor_sync(0xFFFFFFFFu, tqmax, o));
    }
    __shared__ unsigned int smin[16], smax[16];
    int wid = threadIdx.x >> 5;
    int lid = threadIdx.x & 31;
    if (lid == 0) { smin[wid] = tqmin; smax[wid] = tqmax; }
    __syncthreads();
    if (wid == 0) {
        int nwarp = blockDim.x >> 5;
        tqmin = (lid < nwarp) ? smin[lid] : 0xFFFFFFFFu;
        tqmax = (lid < nwarp) ? smax[lid] : 0u;
        #pragma unroll
        for (int o = 8; o > 0; o >>= 1) {
            tqmin = min(tqmin, __shfl_xor_sync(0xFFFFFFFFu, tqmin, o));
            tqmax = max(tqmax, __shfl_xor_sync(0xFFFFFFFFu, tqmax, o));
        }
        if (lid == 0) {
            g_bqmin[blockIdx.x] = tqmin;
            g_bqmax[blockIdx.x] = tqmax;
        }
    }
}

// ---------------------------------------------------------------------------
// Pass 2: exact thresholds; fast path = histogram u16 codes (L2-resident)
// with inline sentinel fixup from ev; slow path = exact re-histogram.
// ---------------------------------------------------------------------------
__global__ __launch_bounds__(THREADS2, 2)
void pass2_kernel(const float4* __restrict__ ev, int n,
                  float* __restrict__ out, float inv_s) {
    __shared__ unsigned int sh[NBINS];
    __shared__ unsigned int wmin[32], wmax[32];
    __shared__ unsigned int s_b[5];
    __shared__ int s_fast;
    __shared__ bool s_last;

    for (int b = threadIdx.x; b < NBINS; b += blockDim.x) sh[b] = 0u;

    // reduce per-block partials
    unsigned int tqmin = 0xFFFFFFFFu, tqmax = 0u;
    for (int b = threadIdx.x; b < BLOCKS; b += blockDim.x) {
        tqmin = min(tqmin, g_bqmin[b]);
        tqmax = max(tqmax, g_bqmax[b]);
    }
    #pragma unroll
    for (int o = 16; o > 0; o >>= 1) {
        tqmin = min(tqmin, __shfl_xor_sync(0xFFFFFFFFu, tqmin, o));
        tqmax = max(tqmax, __shfl_xor_sync(0xFFFFFFFFu, tqmax, o));
    }
    int wid = threadIdx.x >> 5;
    int lid = threadIdx.x & 31;
    if (lid == 0) { wmin[wid] = tqmin; wmax[wid] = tqmax; }
    __syncthreads();
    if (threadIdx.x == 0) {
        int nwarp = blockDim.x >> 5;
        unsigned int m0 = wmin[0], m1 = wmax[0];
        for (int w = 1; w < nwarp; w++) { m0 = min(m0, wmin[w]); m1 = max(m1, wmax[w]); }
        int fast = 1;
        if (m1 > m0) {
            unsigned long long range = (unsigned long long)(m1 - m0);
            for (unsigned long long k = 1; k <= 4; k++) {
                unsigned long long bk = (unsigned long long)m0 + (k * range + 4ull) / 5ull;
                long long dev = (long long)(5ull * bk) - (long long)(k << 21);
                if (dev < -CHECK_DEV || dev > CHECK_DEV) fast = 0;
                s_b[k] = (unsigned int)bk;
            }
        } else {
            // degenerate: raw-t thresholds ceil(k*10*TQ_SCALE)
            s_b[1] = 419431u;  s_b[2] = 838861u;
            s_b[3] = 1258291u; s_b[4] = 1677721u;
        }
        s_fast = fast;
    }
    __syncthreads();
    unsigned int b1 = s_b[1], b2 = s_b[2], b3 = s_b[3], b4 = s_b[4];

    int stride = gridDim.x * blockDim.x;

    if (s_fast) {
        // ---- fast path: u16 codes, 2 x uint4 per iter (16 events) ----
        const uint4* pk4 = reinterpret_cast<const uint4*>(g_code);
        int nq = n >> 3;                          // full uint4s strictly inside n
        int i = blockIdx.x * blockDim.x + threadIdx.x;
        for (; i + stride < nq; i += 2 * stride) {
            uint4 a = pk4[i];
            uint4 b = pk4[i + stride];
            #pragma unroll
            for (int k = 0; k < 4; k++) {
                unsigned int wv = (&a.x)[k];
                unsigned int v0 = wv & 0xFFFFu, v1 = wv >> 16;
                if (v0 != SENT) atomicAdd(&sh[v0], 1u);
                else atomicAdd(&sh[bin_exact(__ldcs(ev + 2 * (4 * i + k)), b1, b2, b3, b4)], 1u);
                if (v1 != SENT) atomicAdd(&sh[v1], 1u);
                else atomicAdd(&sh[bin_exact(__ldcs(ev + 2 * (4 * i + k) + 1), b1, b2, b3, b4)], 1u);
            }
            int ib = i + stride;
            #pragma unroll
            for (int k = 0; k < 4; k++) {
                unsigned int wv = (&b.x)[k];
                unsigned int v0 = wv & 0xFFFFu, v1 = wv >> 16;
                if (v0 != SENT) atomicAdd(&sh[v0], 1u);
                else atomicAdd(&sh[bin_exact(__ldcs(ev + 2 * (4 * ib + k)), b1, b2, b3, b4)], 1u);
                if (v1 != SENT) atomicAdd(&sh[v1], 1u);
                else atomicAdd(&sh[bin_exact(__ldcs(ev + 2 * (4 * ib + k) + 1), b1, b2, b3, b4)], 1u);
            }
        }
        #pragma unroll 1
        for (; i < nq; i += stride) {
            uint4 a = pk4[i];
            #pragma unroll
            for (int k = 0; k < 4; k++) {
                unsigned int wv = (&a.x)[k];
                unsigned int v0 = wv & 0xFFFFu, v1 = wv >> 16;
                if (v0 != SENT) atomicAdd(&sh[v0], 1u);
                else atomicAdd(&sh[bin_exact(__ldcs(ev + 2 * (4 * i + k)), b1, b2, b3, b4)], 1u);
                if (v1 != SENT) atomicAdd(&sh[v1], 1u);
                else atomicAdd(&sh[bin_exact(__ldcs(ev + 2 * (4 * i + k) + 1), b1, b2, b3, b4)], 1u);
            }
        }
        // tail events beyond 8*nq (u16 reads, bounds-guarded by j < n)
        #pragma unroll 1
        for (int j = (nq << 3) + blockIdx.x * blockDim.x + threadIdx.x; j < n; j += stride) {
            unsigned int v = reinterpret_cast<const unsigned short*>(g_code)[j];
            if (v != SENT) atomicAdd(&sh[v], 1u);
            else atomicAdd(&sh[bin_exact(__ldcs(ev + j), b1, b2, b3, b4)], 1u);
        }
        __syncthreads();
        for (int b = threadIdx.x; b < NBINS; b += blockDim.x) {
            unsigned int v = sh[b];
            if (v) atomicAdd(&g_counts[b], v);
        }
    } else {
        // ---- slow path: exact re-histogram from original events ----
        for (int i = blockIdx.x * blockDim.x + threadIdx.x; i < n; i += stride) {
            atomicAdd(&sh[bin_exact(__ldcs(ev + i), b1, b2, b3, b4)], 1u);
        }
        __syncthreads();
        for (int b = threadIdx.x; b < NBINS; b += blockDim.x) {
            unsigned int v = sh[b];
            if (v) atomicAdd(&g_counts2[b], v);
        }
    }

    // ---- last-block finalize ----
    __threadfence();
    __syncthreads();
    if (threadIdx.x == 0) {
        unsigned int t = atomicAdd(&g_done, 1u);
        s_last = (t == gridDim.x - 1);
    }
    __syncthreads();
    if (s_last) {
        __threadfence();
        int fast = s_fast;
        for (int b = threadIdx.x; b < NBINS; b += blockDim.x) {
            unsigned int c = fast ? g_counts[b] : g_counts2[b];
            out[b] = (float)c * inv_s;
        }
    }
}

extern "C" void kernel_launch(void* const* d_in, const int* in_sizes, int n_in,
                              void* d_out, int out_size) {
    const float4* ev = (const float4*)d_in[0];
    int n = in_sizes[0] / 4;              // events: (N, 4) f32, N = 2^24
    float* out = (float*)d_out;

    // every event lands in exactly one bin -> grid.sum() == N exactly
    float inv_s = (n > 0) ? (1.0f / (float)n) : 1.0f;

    pass1_kernel<<<BLOCKS, THREADS1>>>(ev, n);
    pass2_kernel<<<BLOCKS, THREADS2>>>(ev, n, out, inv_s);
}

// round 16
// speedup vs baseline: 1.1850x; 1.0337x over previous
#include <cuda_runtime.h>
#include <cstdint>

#define SGX 32
#define SGY 24
#define SGT 5
#define NBINS (2 * SGT * SGY * SGX)   // 7680

#define BLOCKS   296
#define THREADS1 512                  // pass1 (even blockDim: shfl pairs stay in-warp)
#define THREADS2 1024                 // pass2: full occupancy

#define N_MAX    16777216
#define TQ_MAXI   2097151u
#define TQ_SCALE  (2097151.0f / 50.0f)   // t in [0,50] -> [0, 2^21-1]
#define C_FIXED   (5.0f / 2097152.0f)    // exact 5*2^-21; tq*C_FIXED exact in f32
#define GUARD_U   1280u                  // guard band in u = 5*tq space
#define CHECK_DEV 1000ll                 // |5*bk - k*2^21| <= this  (< GUARD_U)
#define SENT      0xFFFFu

__device__ __align__(16) uint32_t g_code[N_MAX / 2 + 8];  // 32 MB u16-code pairs
__device__ unsigned int g_counts[NBINS];        // fast-path histogram
__device__ unsigned int g_counts2[NBINS];       // slow-path histogram
__device__ unsigned int g_bqmin[BLOCKS];
__device__ unsigned int g_bqmax[BLOCKS];
__device__ unsigned int g_done;

// u16 speculative bin code (SENT if within guard band of fixed threshold
// k*2^21/5), plus quantized t
__device__ __forceinline__ unsigned int decode_code(float4 e, unsigned int& tq) {
    int xv = min(max((int)(e.x * 0.05f), 0), SGX - 1);
    int yv = min(max((int)(e.y * 0.05f), 0), SGY - 1);
    float tf = fmaxf(fmaf(e.z, TQ_SCALE, 0.5f), 0.0f);
    tq = min((unsigned int)tf, TQ_MAXI);
    unsigned int p = (e.w > 0.0f) ? 0u : 1u;
    unsigned int sp = p * 3840u + (unsigned int)yv * 32u + (unsigned int)xv;
    unsigned int u = tq * 5u;
    bool bdry = ((u + GUARD_U) & 0x1FFFFFu) < 2u * GUARD_U;
    int tv = (int)((float)tq * C_FIXED);            // exact floor(5*tq/2^21)
    return bdry ? SENT : ((unsigned int)tv * 768u + sp);
}

// exact-threshold bin from a raw event (sentinel fixup + slow path)
__device__ __forceinline__ int bin_exact(float4 e, unsigned int b1, unsigned int b2,
                                         unsigned int b3, unsigned int b4) {
    int xv = min(max((int)(e.x * 0.05f), 0), SGX - 1);
    int yv = min(max((int)(e.y * 0.05f), 0), SGY - 1);
    float tf = fmaxf(fmaf(e.z, TQ_SCALE, 0.5f), 0.0f);
    unsigned int tq = min((unsigned int)tf, TQ_MAXI);
    unsigned int p = (e.w > 0.0f) ? 0u : 1u;
    int tv = (int)(tq >= b1) + (int)(tq >= b2) + (int)(tq >= b3) + (int)(tq >= b4);
    return tv * 768 + (int)(p * 3840u) + yv * SGX + xv;
}

// ---------------------------------------------------------------------------
// Pass 1: fully-coalesced per-event loads; codes paired across adjacent lanes
// via shfl; even lanes store one u32 (2 codes). qmin/qmax partials; zeroing.
// ---------------------------------------------------------------------------
__global__ __launch_bounds__(THREADS1, 2)
void pass1_kernel(const float4* __restrict__ ev, int n) {
    int gtid = blockIdx.x * blockDim.x + threadIdx.x;
    int stride = gridDim.x * blockDim.x;          // even
    for (int b = gtid; b < NBINS; b += stride) { g_counts[b] = 0u; g_counts2[b] = 0u; }
    if (gtid == 0) g_done = 0u;

    unsigned int tqmin = 0xFFFFFFFFu;
    unsigned int tqmax = 0u;
    const bool evenlane = ((threadIdx.x & 1) == 0);
    int i = gtid;                                  // parity(i) == parity(lane)

    // main loop: 4 independent fully-coalesced LDG.128 per thread
    for (; i + 3 * stride < n; i += 4 * stride) {
        float4 e0 = __ldcs(ev + i);
        float4 e1 = __ldcs(ev + i + stride);
        float4 e2 = __ldcs(ev + i + 2 * stride);
        float4 e3 = __ldcs(ev + i + 3 * stride);
        unsigned int t0, t1, t2, t3;
        unsigned int c0 = decode_code(e0, t0);
        unsigned int c1 = decode_code(e1, t1);
        unsigned int c2 = decode_code(e2, t2);
        unsigned int c3 = decode_code(e3, t3);
        // pair codes with the adjacent (odd) lane; even lanes store packed words
        unsigned int h0 = __shfl_down_sync(0xFFFFFFFFu, c0, 1);
        unsigned int h1 = __shfl_down_sync(0xFFFFFFFFu, c1, 1);
        unsigned int h2 = __shfl_down_sync(0xFFFFFFFFu, c2, 1);
        unsigned int h3 = __shfl_down_sync(0xFFFFFFFFu, c3, 1);
        if (evenlane) {
            g_code[i >> 1]                = c0 | (h0 << 16);
            g_code[(i + stride) >> 1]     = c1 | (h1 << 16);
            g_code[(i + 2 * stride) >> 1] = c2 | (h2 << 16);
            g_code[(i + 3 * stride) >> 1] = c3 | (h3 << 16);
        }
        tqmin = min(tqmin, min(min(t0, t1), min(t2, t3)));
        tqmax = max(tqmax, max(max(t0, t1), max(t2, t3)));
    }
    // tail: per-event u16 stores (coalesced 2B/lane)
    #pragma unroll 1
    for (; i < n; i += stride) {
        float4 e = __ldcs(ev + i);
        unsigned int t;
        reinterpret_cast<unsigned short*>(g_code)[i] =
            (unsigned short)decode_code(e, t);
        tqmin = min(tqmin, t);
        tqmax = max(tqmax, t);
    }

    // block minmax reduce -> per-block partials
    #pragma unroll
    for (int o = 16; o > 0; o >>= 1) {
        tqmin = min(tqmin, __shfl_xor_sync(0xFFFFFFFFu, tqmin, o));
        tqmax = max(tqmax, __shfl_xor_sync(0xFFFFFFFFu, tqmax, o));
    }
    __shared__ unsigned int smin[16], smax[16];
    int wid = threadIdx.x >> 5;
    int lid = threadIdx.x & 31;
    if (lid == 0) { smin[wid] = tqmin; smax[wid] = tqmax; }
    __syncthreads();
    if (wid == 0) {
        int nwarp = blockDim.x >> 5;
        tqmin = (lid < nwarp) ? smin[lid] : 0xFFFFFFFFu;
        tqmax = (lid < nwarp) ? smax[lid] : 0u;
        #pragma unroll
        for (int o = 8; o > 0; o >>= 1) {
            tqmin = min(tqmin, __shfl_xor_sync(0xFFFFFFFFu, tqmin, o));
            tqmax = max(tqmax, __shfl_xor_sync(0xFFFFFFFFu, tqmax, o));
        }
        if (lid == 0) {
            g_bqmin[blockIdx.x] = tqmin;
            g_bqmax[blockIdx.x] = tqmax;
        }
    }
}

// ---------------------------------------------------------------------------
// Pass 2: exact thresholds; fast path = histogram u16 codes (L2-resident)
// with inline sentinel fixup from ev; slow path = exact re-histogram.
// (R13 configuration + nq bounds fix)
// ---------------------------------------------------------------------------
__global__ __launch_bounds__(THREADS2, 2)
void pass2_kernel(const float4* __restrict__ ev, int n,
                  float* __restrict__ out, float inv_s) {
    __shared__ unsigned int sh[NBINS];
    __shared__ unsigned int wmin[32], wmax[32];
    __shared__ unsigned int s_b[5];
    __shared__ int s_fast;
    __shared__ bool s_last;

    for (int b = threadIdx.x; b < NBINS; b += blockDim.x) sh[b] = 0u;

    // reduce per-block partials
    unsigned int tqmin = 0xFFFFFFFFu, tqmax = 0u;
    for (int b = threadIdx.x; b < BLOCKS; b += blockDim.x) {
        tqmin = min(tqmin, g_bqmin[b]);
        tqmax = max(tqmax, g_bqmax[b]);
    }
    #pragma unroll
    for (int o = 16; o > 0; o >>= 1) {
        tqmin = min(tqmin, __shfl_xor_sync(0xFFFFFFFFu, tqmin, o));
        tqmax = max(tqmax, __shfl_xor_sync(0xFFFFFFFFu, tqmax, o));
    }
    int wid = threadIdx.x >> 5;
    int lid = threadIdx.x & 31;
    if (lid == 0) { wmin[wid] = tqmin; wmax[wid] = tqmax; }
    __syncthreads();
    if (threadIdx.x == 0) {
        int nwarp = blockDim.x >> 5;
        unsigned int m0 = wmin[0], m1 = wmax[0];
        for (int w = 1; w < nwarp; w++) { m0 = min(m0, wmin[w]); m1 = max(m1, wmax[w]); }
        int fast = 1;
        if (m1 > m0) {
            unsigned long long range = (unsigned long long)(m1 - m0);
            for (unsigned long long k = 1; k <= 4; k++) {
                unsigned long long bk = (unsigned long long)m0 + (k * range + 4ull) / 5ull;
                long long dev = (long long)(5ull * bk) - (long long)(k << 21);
                if (dev < -CHECK_DEV || dev > CHECK_DEV) fast = 0;
                s_b[k] = (unsigned int)bk;
            }
        } else {
            // degenerate: raw-t thresholds ceil(k*10*TQ_SCALE)
            s_b[1] = 419431u;  s_b[2] = 838861u;
            s_b[3] = 1258291u; s_b[4] = 1677721u;
        }
        s_fast = fast;
    }
    __syncthreads();
    unsigned int b1 = s_b[1], b2 = s_b[2], b3 = s_b[3], b4 = s_b[4];

    int stride = gridDim.x * blockDim.x;

    if (s_fast) {
        // ---- fast path: u16 codes, 2 x uint4 per iter (16 events) ----
        const uint4* pk4 = reinterpret_cast<const uint4*>(g_code);
        int nq = n >> 3;                          // full uint4s strictly inside n
        int i = blockIdx.x * blockDim.x + threadIdx.x;
        for (; i + stride < nq; i += 2 * stride) {
            uint4 a = pk4[i];
            uint4 b = pk4[i + stride];
            #pragma unroll
            for (int k = 0; k < 4; k++) {
                unsigned int wv = (&a.x)[k];
                unsigned int v0 = wv & 0xFFFFu, v1 = wv >> 16;
                if (v0 != SENT) atomicAdd(&sh[v0], 1u);
                else atomicAdd(&sh[bin_exact(__ldcs(ev + 2 * (4 * i + k)), b1, b2, b3, b4)], 1u);
                if (v1 != SENT) atomicAdd(&sh[v1], 1u);
                else atomicAdd(&sh[bin_exact(__ldcs(ev + 2 * (4 * i + k) + 1), b1, b2, b3, b4)], 1u);
            }
            int ib = i + stride;
            #pragma unroll
            for (int k = 0; k < 4; k++) {
                unsigned int wv = (&b.x)[k];
                unsigned int v0 = wv & 0xFFFFu, v1 = wv >> 16;
                if (v0 != SENT) atomicAdd(&sh[v0], 1u);
                else atomicAdd(&sh[bin_exact(__ldcs(ev + 2 * (4 * ib + k)), b1, b2, b3, b4)], 1u);
                if (v1 != SENT) atomicAdd(&sh[v1], 1u);
                else atomicAdd(&sh[bin_exact(__ldcs(ev + 2 * (4 * ib + k) + 1), b1, b2, b3, b4)], 1u);
            }
        }
        #pragma unroll 1
        for (; i < nq; i += stride) {
            uint4 a = pk4[i];
            #pragma unroll
            for (int k = 0; k < 4; k++) {
                unsigned int wv = (&a.x)[k];
                unsigned int v0 = wv & 0xFFFFu, v1 = wv >> 16;
                if (v0 != SENT) atomicAdd(&sh[v0], 1u);
                else atomicAdd(&sh[bin_exact(__ldcs(ev + 2 * (4 * i + k)), b1, b2, b3, b4)], 1u);
                if (v1 != SENT) atomicAdd(&sh[v1], 1u);
                else atomicAdd(&sh[bin_exact(__ldcs(ev + 2 * (4 * i + k) + 1), b1, b2, b3, b4)], 1u);
            }
        }
        // tail events beyond 8*nq (u16 reads, bounds-guarded by j < n)
        #pragma unroll 1
        for (int j = (nq << 3) + blockIdx.x * blockDim.x + threadIdx.x; j < n; j += stride) {
            unsigned int v = reinterpret_cast<const unsigned short*>(g_code)[j];
            if (v != SENT) atomicAdd(&sh[v], 1u);
            else atomicAdd(&sh[bin_exact(__ldcs(ev + j), b1, b2, b3, b4)], 1u);
        }
        __syncthreads();
        for (int b = threadIdx.x; b < NBINS; b += blockDim.x) {
            unsigned int v = sh[b];
            if (v) atomicAdd(&g_counts[b], v);
        }
    } else {
        // ---- slow path: exact re-histogram from original events ----
        for (int i = blockIdx.x * blockDim.x + threadIdx.x; i < n; i += stride) {
            atomicAdd(&sh[bin_exact(__ldcs(ev + i), b1, b2, b3, b4)], 1u);
        }
        __syncthreads();
        for (int b = threadIdx.x; b < NBINS; b += blockDim.x) {
            unsigned int v = sh[b];
            if (v) atomicAdd(&g_counts2[b], v);
        }
    }

    // ---- last-block finalize ----
    __threadfence();
    __syncthreads();
    if (threadIdx.x == 0) {
        unsigned int t = atomicAdd(&g_done, 1u);
        s_last = (t == gridDim.x - 1);
    }
    __syncthreads();
    if (s_last) {
        __threadfence();
        int fast = s_fast;
        for (int b = threadIdx.x; b < NBINS; b += blockDim.x) {
            unsigned int c = fast ? g_counts[b] : g_counts2[b];
            out[b] = (float)c * inv_s;
        }
    }
}

extern "C" void kernel_launch(void* const* d_in, const int* in_sizes, int n_in,
                              void* d_out, int out_size) {
    const float4* ev = (const float4*)d_in[0];
    int n = in_sizes[0] / 4;              // events: (N, 4) f32, N = 2^24
    float* out = (float*)d_out;

    // every event lands in exactly one bin -> grid.sum() == N exactly
    float inv_s = (n > 0) ? (1.0f / (float)n) : 1.0f;

    pass1_kernel<<<BLOCKS, THREADS1>>>(ev, n);
    pass2_kernel<<<BLOCKS, THREADS2>>>(ev, n, out, inv_s);
}